// round 8
// baseline (speedup 1.0000x reference)
#include <cuda_runtime.h>

#define BB 4
#define NN 20000
#define EE 320000
#define IND 21
#define ED 64
#define H2 128
#define NL 3
#define BN_EPS 1e-5f

#define HSZ  (BB*NN*ED)
#define H2SZ (BB*NN*H2)

// packed fp32x2 helpers (FFMA2 path — bit-exact dual fp32 FMA)
#define FMA2(acc, a, b) \
    asm("fma.rn.f32x2 %0, %1, %2, %0;" : "+l"(acc) : "l"(a), "l"(b))
#define PK2(out, x) \
    asm("mov.b64 %0, {%1, %1};" : "=l"(out) : "r"(__float_as_uint(x)))
#define UNPK(lo, hi, v) \
    { unsigned int _l, _h; asm("mov.b64 {%0, %1}, %2;" : "=r"(_l), "=r"(_h) : "l"(v)); \
      lo = __uint_as_float(_l); hi = __uint_as_float(_h); }

// ---- scratch that must be zero at specific points; zeroing is folded into
//      spare blocks of existing kernels (see k_offuv / k_gemm2 final) ----
struct ZBuf {
    float sc[2*BB*NN];     // interleaved {attr-sum, deg}; zero before k_prep
    int   fill[BB*NN];     // zero before k_place
    int   ctr[BB];         // zero before k_offuv
    float sum[NL*BB*H2];   // zero before gemm1 l=0  (cleared in k_offuv)
    float sumsq[NL*BB*H2];
};
__device__ ZBuf gz;        // zero-initialized at module load (first call OK)
#define ZHEAD_WORDS (2*BB*NN + BB*NN + BB)        // sc+fill+ctr = 240,004
#define ZTAIL_WORDS (2*NL*BB*H2)                  // sum+sumsq   = 3,072

__device__ int   g_src[BB*EE];
__device__ int   g_dst[BB*EE];
__device__ int   g_off[BB*NN];
__device__ int   g_csr[BB*EE];
__device__ float g_h0[HSZ];
__device__ float g_h1[HSZ];
__device__ float g_h2[H2SZ];
__device__ float g_u[NL*H2];
__device__ float g_v[NL*H2];

// ---- launch 0: decode indices (self dtype-detect) + per-node {attr-sum, deg} ----
#define BPG (EE/512)                 // 625 blocks per graph
#define PREP_BLOCKS (BB*EE/512)      // 2500
__global__ void __launch_bounds__(256) k_prep(const void* __restrict__ ei,
                                              const float* __restrict__ ea) {
    __shared__ unsigned int sOr[256];
    int tid = threadIdx.x;
    // dtype probe: first 256 odd 32-bit words (within min-size buffer; int64 -> all 0)
    sOr[tid] = ((const unsigned int*)ei)[2 * tid + 1];
    __syncthreads();
    for (int s = 128; s > 0; s >>= 1) {
        if (tid < s) sOr[tid] |= sOr[tid + s];
        __syncthreads();
    }
    bool is64 = (sOr[0] == 0u);

    int b  = blockIdx.x / BPG;
    int e0 = (blockIdx.x - b * BPG) * 512;
    int idx = b * EE + e0 + 2 * tid;          // first of this thread's 2 edges
    int src0, src1, dst0, dst1;
    if (is64) {
        const longlong2* pS = (const longlong2*)((const long long*)ei
                              + (long long)b * 2 * EE + e0) + tid;
        const longlong2* pD = (const longlong2*)((const long long*)ei
                              + (long long)b * 2 * EE + EE + e0) + tid;
        longlong2 s2 = *pS, d2 = *pD;
        src0 = (int)s2.x; src1 = (int)s2.y;
        dst0 = (int)d2.x; dst1 = (int)d2.y;
    } else {
        const int2* pS = (const int2*)((const int*)ei + (long long)b * 2 * EE + e0) + tid;
        const int2* pD = (const int2*)((const int*)ei + (long long)b * 2 * EE + EE + e0) + tid;
        int2 s2 = *pS, d2 = *pD;
        src0 = s2.x; src1 = s2.y;
        dst0 = d2.x; dst1 = d2.y;
    }
    ((int2*)g_src)[idx >> 1] = make_int2(src0, src1);
    ((int2*)g_dst)[idx >> 1] = make_int2(dst0, dst1);
    float2 a2 = ((const float2*)ea)[idx >> 1];
    float* p0 = &gz.sc[2 * (b * NN + dst0)];
    float* p1 = &gz.sc[2 * (b * NN + dst1)];
    asm volatile("red.global.add.v2.f32 [%0], {%1,%2};"
                 :: "l"(p0), "f"(a2.x), "f"(1.0f) : "memory");
    asm volatile("red.global.add.v2.f32 [%0], {%1,%2};"
                 :: "l"(p1), "f"(a2.y), "f"(1.0f) : "memory");
}

// ---- launch 1: CSR offsets (warp-aggregated) + rank-2 uv fold + zero sum/sumsq ----
#define OFF_BLOCKS ((BB*NN + 255) / 256)   // 313
__global__ void __launch_bounds__(256) k_offuv(const float* __restrict__ edgeW,
                                               const float* __restrict__ edgeb,
                                               const float* __restrict__ W1) {
    if (blockIdx.x < OFF_BLOCKS) {
        int i = blockIdx.x * 256 + threadIdx.x;
        if (i < BB * NN) {               // full warps only: 32 | 20000
            int b = i / NN;              // uniform within a warp
            int c = (int)gz.sc[2 * i + 1];
            int lane = threadIdx.x & 31;
            int pref = c;
#pragma unroll
            for (int d = 1; d < 32; d <<= 1) {
                int t = __shfl_up_sync(0xFFFFFFFFu, pref, d);
                if (lane >= d) pref += t;
            }
            int total = __shfl_sync(0xFFFFFFFFu, pref, 31);
            int base = 0;
            if (lane == 31) base = atomicAdd(&gz.ctr[b], total);
            base = __shfl_sync(0xFFFFFFFFu, base, 31);
            g_off[i] = b * EE + base + pref - c;
        }
    } else if (blockIdx.x < OFF_BLOCKS + NL) {
        int l = blockIdx.x - OFF_BLOCKS;           // 0..NL-1
        __shared__ float su[2][128], sv[2][128];
        int j = threadIdx.x & 127, hf = threadIdx.x >> 7;
        const float* Wl = W1 + l * H2 * H2;
        float u = 0.f, v = 0.f;
#pragma unroll 8
        for (int c = hf * 32; c < hf * 32 + 32; c++) {
            float wv = Wl[(ED + c) * H2 + j];
            u += edgeW[l * ED + c] * wv;
            v += edgeb[l * ED + c] * wv;
        }
        su[hf][j] = u; sv[hf][j] = v;
        __syncthreads();
        if (hf == 0) {
            g_u[l * H2 + j] = su[0][j] + su[1][j];
            g_v[l * H2 + j] = sv[0][j] + sv[1][j];
        }
    } else {
        // zero sum/sumsq for this call's gemm1 atomics (prev call's gemm2s done)
        int4* p = (int4*)gz.sum;
        for (int i = threadIdx.x; i < ZTAIL_WORDS / 4; i += 256)
            p[i] = make_int4(0, 0, 0, 0);
    }
}

// ---- launch 2: CSR placement + input embedding (fused, disjoint block ranges) ----
#define PLACE_BLOCKS (BB*EE / 256)   // 5000
#define EMB_BLOCKS   (BB*NN / 64)    // 1250
__global__ void __launch_bounds__(256) k_place(const float* __restrict__ x,
                                               const float* __restrict__ inW,
                                               const float* __restrict__ inb) {
    if (blockIdx.x < PLACE_BLOCKS) {
        int idx = blockIdx.x * 256 + threadIdx.x;
        int b = idx / EE;
        int dst = g_dst[idx];
        int r = atomicAdd(&gz.fill[b * NN + dst], 1);
        g_csr[g_off[b * NN + dst] + r] = g_src[idx];
    } else {
        __shared__ float sW[IND * ED];
        __shared__ float sX[64 * IND];
        int nid0 = (blockIdx.x - PLACE_BLOCKS) * 64;
        int tid = threadIdx.x;
        for (int i = tid; i < IND * ED; i += 256) sW[i] = inW[i];
        for (int i = tid; i < 64 * IND; i += 256) sX[i] = x[(long long)nid0 * IND + i];
        __syncthreads();
        int j = tid & 63;
        float bj = inb[j];
        for (int loc = tid >> 6; loc < 64; loc += 4) {
            float acc = bj;
#pragma unroll
            for (int i = 0; i < IND; i++) acc += sX[loc * IND + i] * sW[i * ED + j];
            g_h0[(long long)(nid0 + loc) * ED + j] = acc;
        }
    }
}

// ---- launch 3 (PROFILED): GEMM1 (fused gather-aggregate, FFMA2 mainloop):
//      h2 = seg_sum(h[src]) @ W1[0:64,:] + s*u + deg*v + b1 ; fused BN stats ----
#define ST1 66
#define G1_SMEMF (8192 + 64*ST1 + 64 + 64 + 64 + 128*5)
__global__ void __launch_bounds__(256) k_gemm1(const float* __restrict__ W1l,
                                               const float* __restrict__ b1l,
                                               const float* __restrict__ hin,
                                               int l) {
    extern __shared__ float sm[];
    float* sW   = sm;                  // 64 x 128
    float* sInT = sW + 8192;           // 64 k x 66 rows (transposed, 8B-aligned pairs)
    float* sS   = sInT + 64 * ST1;
    int*   sOff = (int*)(sS + 64);
    int*   sCnt = sOff + 64;
    float* sU   = (float*)(sCnt + 64);
    float* sV   = sU + 128;
    float* sB   = sV + 128;
    float* sSum = sB + 128;
    float* sSqs = sSum + 128;

    int tid = threadIdx.x;
    int b = blockIdx.y;
    int row0 = blockIdx.x * 64;
    int nrows = NN - row0; if (nrows > 64) nrows = 64;

    for (int i = tid; i < 2048; i += 256) ((float4*)sW)[i] = ((const float4*)W1l)[i];
    for (int i = tid; i < 128; i += 256) {
        sU[i] = g_u[l * H2 + i]; sV[i] = g_v[l * H2 + i]; sB[i] = b1l[i];
        sSum[i] = 0.f; sSqs[i] = 0.f;
    }
    if (tid < 64) {
        int ok = tid < nrows;
        int i = b * NN + row0 + tid;
        sOff[tid] = ok ? g_off[i] : 0;
        sCnt[tid] = ok ? (int)gz.sc[2 * i + 1] : 0;
        sS[tid]   = ok ? gz.sc[2 * i] : 0.f;
    }
    __syncthreads();

    // gather + segment-sum straight from h; write TRANSPOSED into sInT[k][row]
    {
        int q4 = (tid & 15) * 4;
        int g = tid >> 4;
        const float* hb = hin + (long long)b * NN * ED;
#pragma unroll
        for (int rr = g * 4; rr < g * 4 + 4; rr++) {
            int off = sOff[rr], c = sCnt[rr];
            float ax = 0.f, ay = 0.f, az = 0.f, aw = 0.f;
            for (int e = 0; e < c; e++) {
                int src = g_csr[off + e];
                float4 v = *(const float4*)(hb + (long long)src * ED + q4);
                ax += v.x; ay += v.y; az += v.z; aw += v.w;
            }
            sInT[(q4 + 0) * ST1 + rr] = ax;
            sInT[(q4 + 1) * ST1 + rr] = ay;
            sInT[(q4 + 2) * ST1 + rr] = az;
            sInT[(q4 + 3) * ST1 + rr] = aw;
        }
    }
    __syncthreads();

    int cq = tid & 31, rg = tid >> 5;   // 32 colquads x 8 rowgroups(8 rows)
    unsigned long long acc2[4][4];      // [rowpair][col]
#pragma unroll
    for (int p = 0; p < 4; p++)
        acc2[p][0] = acc2[p][1] = acc2[p][2] = acc2[p][3] = 0ull;

#pragma unroll 8
    for (int k = 0; k < 64; k++) {
        float4 w = *(const float4*)(sW + k * 128 + cq * 4);
        unsigned long long wb0, wb1, wb2, wb3;
        PK2(wb0, w.x); PK2(wb1, w.y); PK2(wb2, w.z); PK2(wb3, w.w);
        const unsigned long long* arow =
            (const unsigned long long*)(sInT + k * ST1 + rg * 8);
#pragma unroll
        for (int p = 0; p < 4; p++) {
            unsigned long long ap = arow[p];
            FMA2(acc2[p][0], ap, wb0);
            FMA2(acc2[p][1], ap, wb1);
            FMA2(acc2[p][2], ap, wb2);
            FMA2(acc2[p][3], ap, wb3);
        }
    }

    float u0 = sU[cq*4], u1 = sU[cq*4+1], u2 = sU[cq*4+2], u3 = sU[cq*4+3];
    float v0 = sV[cq*4], v1 = sV[cq*4+1], v2 = sV[cq*4+2], v3 = sV[cq*4+3];
    float bb0 = sB[cq*4], bb1 = sB[cq*4+1], bb2 = sB[cq*4+2], bb3 = sB[cq*4+3];
    float ps0=0,ps1=0,ps2=0,ps3=0, pq0=0,pq1=0,pq2=0,pq3=0;
    float* obase = g_h2 + ((long long)b * NN + row0) * H2;
#pragma unroll
    for (int p = 0; p < 4; p++) {
        float o_[2][4];
        UNPK(o_[0][0], o_[1][0], acc2[p][0]);
        UNPK(o_[0][1], o_[1][1], acc2[p][1]);
        UNPK(o_[0][2], o_[1][2], acc2[p][2]);
        UNPK(o_[0][3], o_[1][3], acc2[p][3]);
#pragma unroll
        for (int t = 0; t < 2; t++) {
            int rr = rg * 8 + 2 * p + t;
            if (rr < nrows) {
                float s = sS[rr], d = (float)sCnt[rr];
                float o0 = o_[t][0] + s*u0 + d*v0 + bb0;
                float o1 = o_[t][1] + s*u1 + d*v1 + bb1;
                float o2 = o_[t][2] + s*u2 + d*v2 + bb2;
                float o3 = o_[t][3] + s*u3 + d*v3 + bb3;
                float4 o = {o0, o1, o2, o3};
                *(float4*)(obase + rr * H2 + cq * 4) = o;
                ps0 += o0; ps1 += o1; ps2 += o2; ps3 += o3;
                pq0 += o0*o0; pq1 += o1*o1; pq2 += o2*o2; pq3 += o3*o3;
            }
        }
    }
    atomicAdd(sSum + cq*4,     ps0); atomicAdd(sSum + cq*4 + 1, ps1);
    atomicAdd(sSum + cq*4 + 2, ps2); atomicAdd(sSum + cq*4 + 3, ps3);
    atomicAdd(sSqs + cq*4,     pq0); atomicAdd(sSqs + cq*4 + 1, pq1);
    atomicAdd(sSqs + cq*4 + 2, pq2); atomicAdd(sSqs + cq*4 + 3, pq3);
    __syncthreads();
    float* gsum = gz.sum   + l * BB * H2 + b * H2;
    float* gsq  = gz.sumsq + l * BB * H2 + b * H2;
    for (int i = tid; i < 128; i += 256) {
        atomicAdd(&gsum[i], sSum[i]);
        atomicAdd(&gsq[i],  sSqs[i]);
    }
}

// ---- GEMM2 (BN finalize fused, FFMA2 mainloop): out = relu?(relu(BN(h2)) @ W2 + b2)
//      final-layer launch carries 32 extra blocks that zero sc/fill/ctr ----
#define ST2 66
#define ZCLR_BLOCKS 32
#define G2_SMEMF (8192 + 128*ST2 + 256)
__global__ void __launch_bounds__(256) k_gemm2(const float* __restrict__ W2l,
                                               const float* __restrict__ b2l,
                                               const float* __restrict__ gm,
                                               const float* __restrict__ bt,
                                               float* __restrict__ hout,
                                               int l, int relu_out) {
    int tid = threadIdx.x, b = blockIdx.y;
    if (blockIdx.x >= (NN + 63) / 64) {        // final-launch scratch clear
        if (b != 0) return;
        int4* p = (int4*)gz.sc;                // sc+fill+ctr contiguous head
        int zb = blockIdx.x - (NN + 63) / 64;
        for (int i = zb * 256 + tid; i < ZHEAD_WORDS / 4; i += ZCLR_BLOCKS * 256)
            p[i] = make_int4(0, 0, 0, 0);
        return;
    }
    extern __shared__ float sm[];
    float* sW   = sm;             // 128 x 64
    float* sInT = sW + 8192;      // 128 k x 66 rows (transposed)
    float* sA   = sInT + 128 * ST2;
    float* sC   = sA + 128;
    int row0 = blockIdx.x * 64;
    int nrows = NN - row0; if (nrows > 64) nrows = 64;

    for (int i = tid; i < 2048; i += 256) ((float4*)sW)[i] = ((const float4*)W2l)[i];
    const float* gsum = gz.sum   + l * BB * H2 + b * H2;
    const float* gsq  = gz.sumsq + l * BB * H2 + b * H2;
    for (int i = tid; i < 128; i += 256) {
        float mean = gsum[i] * (1.0f / NN);
        float var  = gsq[i] * (1.0f / NN) - mean * mean;
        float a = gm[i] * rsqrtf(var + BN_EPS);
        sA[i] = a;
        sC[i] = bt[i] - mean * a;
    }
    __syncthreads();

    // stage BN(h2)+relu TRANSPOSED: r = i&63 (warp-consecutive => conflict-free STS)
    const float* ibase = g_h2 + ((long long)b * NN + row0) * H2;
    for (int i = tid; i < 2048; i += 256) {
        int r = i & 63, k4 = i >> 6;   // k4 in 0..31
        float4 v;
        if (r < nrows) {
            v = ((const float4*)ibase)[r * 32 + k4];
            float4 a4 = ((const float4*)sA)[k4];
            float4 c4 = ((const float4*)sC)[k4];
            v.x = fmaxf(v.x * a4.x + c4.x, 0.f);
            v.y = fmaxf(v.y * a4.y + c4.y, 0.f);
            v.z = fmaxf(v.z * a4.z + c4.z, 0.f);
            v.w = fmaxf(v.w * a4.w + c4.w, 0.f);
        } else v = make_float4(0.f, 0.f, 0.f, 0.f);
        sInT[(k4 * 4 + 0) * ST2 + r] = v.x;
        sInT[(k4 * 4 + 1) * ST2 + r] = v.y;
        sInT[(k4 * 4 + 2) * ST2 + r] = v.z;
        sInT[(k4 * 4 + 3) * ST2 + r] = v.w;
    }
    __syncthreads();

    int cq = tid & 15, rg = tid >> 4;   // 16 colquads x 16 rowgroups(4 rows)
    unsigned long long acc2[2][4];
#pragma unroll
    for (int p = 0; p < 2; p++)
        acc2[p][0] = acc2[p][1] = acc2[p][2] = acc2[p][3] = 0ull;

#pragma unroll 8
    for (int k = 0; k < 128; k++) {
        float4 w = *(const float4*)(sW + k * 64 + cq * 4);
        unsigned long long wb0, wb1, wb2, wb3;
        PK2(wb0, w.x); PK2(wb1, w.y); PK2(wb2, w.z); PK2(wb3, w.w);
        const unsigned long long* arow =
            (const unsigned long long*)(sInT + k * ST2 + rg * 4);
#pragma unroll
        for (int p = 0; p < 2; p++) {
            unsigned long long ap = arow[p];
            FMA2(acc2[p][0], ap, wb0);
            FMA2(acc2[p][1], ap, wb1);
            FMA2(acc2[p][2], ap, wb2);
            FMA2(acc2[p][3], ap, wb3);
        }
    }

    float4 bb = ((const float4*)b2l)[cq];
    float* obase = hout + ((long long)b * NN + row0) * ED;
#pragma unroll
    for (int p = 0; p < 2; p++) {
        float o_[2][4];
        UNPK(o_[0][0], o_[1][0], acc2[p][0]);
        UNPK(o_[0][1], o_[1][1], acc2[p][1]);
        UNPK(o_[0][2], o_[1][2], acc2[p][2]);
        UNPK(o_[0][3], o_[1][3], acc2[p][3]);
#pragma unroll
        for (int t = 0; t < 2; t++) {
            int rr = rg * 4 + 2 * p + t;
            if (rr < nrows) {
                float4 o = {o_[t][0] + bb.x, o_[t][1] + bb.y,
                            o_[t][2] + bb.z, o_[t][3] + bb.w};
                if (relu_out) {
                    o.x = fmaxf(o.x, 0.f); o.y = fmaxf(o.y, 0.f);
                    o.z = fmaxf(o.z, 0.f); o.w = fmaxf(o.w, 0.f);
                }
                *(float4*)(obase + rr * ED + cq * 4) = o;
            }
        }
    }
}

extern "C" void kernel_launch(void* const* d_in, const int* in_sizes, int n_in,
                              void* d_out, int out_size) {
    const float* x     = (const float*)d_in[0];
    const void*  ei    = d_in[1];
    const float* ea    = (const float*)d_in[2];
    const float* inW   = (const float*)d_in[3];
    const float* inb   = (const float*)d_in[4];
    const float* edgeW = (const float*)d_in[5];
    const float* edgeb = (const float*)d_in[6];
    const float* W1    = (const float*)d_in[7];
    const float* b1    = (const float*)d_in[8];
    const float* gamma = (const float*)d_in[9];
    const float* beta  = (const float*)d_in[10];
    const float* W2    = (const float*)d_in[11];
    const float* b2    = (const float*)d_in[12];
    float* out = (float*)d_out;

    void *ph0, *ph1;
    cudaGetSymbolAddress(&ph0, g_h0);
    cudaGetSymbolAddress(&ph1, g_h1);

    cudaFuncSetAttribute(k_gemm1, cudaFuncAttributeMaxDynamicSharedMemorySize, G1_SMEMF * 4);
    cudaFuncSetAttribute(k_gemm2, cudaFuncAttributeMaxDynamicSharedMemorySize, G2_SMEMF * 4);

    k_prep<<<PREP_BLOCKS, 256>>>(ei, ea);                        // 0
    k_offuv<<<OFF_BLOCKS + NL + 1, 256>>>(edgeW, edgeb, W1);     // 1
    k_place<<<PLACE_BLOCKS + EMB_BLOCKS, 256>>>(x, inW, inb);    // 2

    const float* hin = (const float*)ph0;
    for (int l = 0; l < NL; l++) {
        dim3 g1((NN + 63) / 64, BB);
        k_gemm1<<<g1, 256, G1_SMEMF * 4>>>(W1 + l * H2 * H2, b1 + l * H2, hin, l); // 3 at l=0
        float* hout = (l == NL - 1) ? out : ((l == 0) ? (float*)ph1 : (float*)ph0);
        int fin = (l == NL - 1);
        dim3 g2((NN + 63) / 64 + (fin ? ZCLR_BLOCKS : 0), BB);
        k_gemm2<<<g2, 256, G2_SMEMF * 4>>>(W2 + l * H2 * ED, b2 + l * ED,
                                           gamma + l * H2, beta + l * H2,
                                           hout, l, (l < NL - 1) ? 1 : 0);
        hin = hout;
    }
}

// round 10
// speedup vs baseline: 1.0501x; 1.0501x over previous
#include <cuda_runtime.h>

#define BB 4
#define NN 20000
#define EE 320000
#define IND 21
#define ED 64
#define H2 128
#define NL 3
#define BN_EPS 1e-5f

#define HSZ  (BB*NN*ED)
#define H2SZ (BB*NN*H2)

// packed fp32x2 helpers (FFMA2 path — bit-exact dual fp32 FMA)
#define FMA2(acc, a, b) \
    asm("fma.rn.f32x2 %0, %1, %2, %0;" : "+l"(acc) : "l"(a), "l"(b))
#define PK2(out, x) \
    asm("mov.b64 %0, {%1, %1};" : "=l"(out) : "r"(__float_as_uint(x)))
#define UNPK(lo, hi, v) \
    { unsigned int _l, _h; asm("mov.b64 {%0, %1}, %2;" : "=r"(_l), "=r"(_h) : "l"(v)); \
      lo = __uint_as_float(_l); hi = __uint_as_float(_h); }

// ---- scratch that must be zero at specific points; zeroing is folded into
//      spare blocks of existing kernels (see k_offuv / k_gemm2 final) ----
struct ZBuf {
    float sc[2*BB*NN];     // interleaved {attr-sum, deg}; zero before k_prep
    int   fill[BB*NN];     // zero before k_place
    int   ctr[BB];         // zero before k_offuv
    float sum[NL*BB*H2];   // zero before gemm1 l=0  (cleared in k_offuv)
    float sumsq[NL*BB*H2];
};
__device__ ZBuf gz;        // zero-initialized at module load (first call OK)
#define ZHEAD_WORDS (2*BB*NN + BB*NN + BB)        // sc+fill+ctr = 240,004
#define ZTAIL_WORDS (2*NL*BB*H2)                  // sum+sumsq   = 3,072

__device__ int   g_src[BB*EE];
__device__ int   g_dst[BB*EE];
__device__ int   g_off[BB*NN];
__device__ int   g_csr[BB*EE];
__device__ float g_h0[HSZ];
__device__ float g_h1[HSZ];
__device__ float g_h2[H2SZ];
__device__ float g_u[NL*H2];
__device__ float g_v[NL*H2];

// ---- launch 0: decode indices (self dtype-detect) + per-node {attr-sum, deg} ----
#define BPG (EE/512)                 // 625 blocks per graph
#define PREP_BLOCKS (BB*EE/512)      // 2500
__global__ void __launch_bounds__(256) k_prep(const void* __restrict__ ei,
                                              const float* __restrict__ ea) {
    __shared__ unsigned int sOr[256];
    int tid = threadIdx.x;
    // dtype probe: first 256 odd 32-bit words (within min-size buffer; int64 -> all 0)
    sOr[tid] = ((const unsigned int*)ei)[2 * tid + 1];
    __syncthreads();
    for (int s = 128; s > 0; s >>= 1) {
        if (tid < s) sOr[tid] |= sOr[tid + s];
        __syncthreads();
    }
    bool is64 = (sOr[0] == 0u);

    int b  = blockIdx.x / BPG;
    int e0 = (blockIdx.x - b * BPG) * 512;
    int idx = b * EE + e0 + 2 * tid;          // first of this thread's 2 edges
    int src0, src1, dst0, dst1;
    if (is64) {
        const longlong2* pS = (const longlong2*)((const long long*)ei
                              + (long long)b * 2 * EE + e0) + tid;
        const longlong2* pD = (const longlong2*)((const long long*)ei
                              + (long long)b * 2 * EE + EE + e0) + tid;
        longlong2 s2 = *pS, d2 = *pD;
        src0 = (int)s2.x; src1 = (int)s2.y;
        dst0 = (int)d2.x; dst1 = (int)d2.y;
    } else {
        const int2* pS = (const int2*)((const int*)ei + (long long)b * 2 * EE + e0) + tid;
        const int2* pD = (const int2*)((const int*)ei + (long long)b * 2 * EE + EE + e0) + tid;
        int2 s2 = *pS, d2 = *pD;
        src0 = s2.x; src1 = s2.y;
        dst0 = d2.x; dst1 = d2.y;
    }
    ((int2*)g_src)[idx >> 1] = make_int2(src0, src1);
    ((int2*)g_dst)[idx >> 1] = make_int2(dst0, dst1);
    float2 a2 = ((const float2*)ea)[idx >> 1];
    float* p0 = &gz.sc[2 * (b * NN + dst0)];
    float* p1 = &gz.sc[2 * (b * NN + dst1)];
    asm volatile("red.global.add.v2.f32 [%0], {%1,%2};"
                 :: "l"(p0), "f"(a2.x), "f"(1.0f) : "memory");
    asm volatile("red.global.add.v2.f32 [%0], {%1,%2};"
                 :: "l"(p1), "f"(a2.y), "f"(1.0f) : "memory");
}

// ---- launch 1: CSR offsets (warp-aggregated) + rank-2 uv fold + zero sum/sumsq ----
#define OFF_BLOCKS ((BB*NN + 255) / 256)   // 313
__global__ void __launch_bounds__(256) k_offuv(const float* __restrict__ edgeW,
                                               const float* __restrict__ edgeb,
                                               const float* __restrict__ W1) {
    if (blockIdx.x < OFF_BLOCKS) {
        int i = blockIdx.x * 256 + threadIdx.x;
        if (i < BB * NN) {               // full warps only: 32 | 20000
            int b = i / NN;              // uniform within a warp
            int c = (int)gz.sc[2 * i + 1];
            int lane = threadIdx.x & 31;
            int pref = c;
#pragma unroll
            for (int d = 1; d < 32; d <<= 1) {
                int t = __shfl_up_sync(0xFFFFFFFFu, pref, d);
                if (lane >= d) pref += t;
            }
            int total = __shfl_sync(0xFFFFFFFFu, pref, 31);
            int base = 0;
            if (lane == 31) base = atomicAdd(&gz.ctr[b], total);
            base = __shfl_sync(0xFFFFFFFFu, base, 31);
            g_off[i] = b * EE + base + pref - c;
        }
    } else if (blockIdx.x < OFF_BLOCKS + NL) {
        int l = blockIdx.x - OFF_BLOCKS;           // 0..NL-1
        __shared__ float su[2][128], sv[2][128];
        int j = threadIdx.x & 127, hf = threadIdx.x >> 7;
        const float* Wl = W1 + l * H2 * H2;
        float u = 0.f, v = 0.f;
#pragma unroll 8
        for (int c = hf * 32; c < hf * 32 + 32; c++) {
            float wv = Wl[(ED + c) * H2 + j];
            u += edgeW[l * ED + c] * wv;
            v += edgeb[l * ED + c] * wv;
        }
        su[hf][j] = u; sv[hf][j] = v;
        __syncthreads();
        if (hf == 0) {
            g_u[l * H2 + j] = su[0][j] + su[1][j];
            g_v[l * H2 + j] = sv[0][j] + sv[1][j];
        }
    } else {
        // zero sum/sumsq for this call's gemm1 atomics (prev call's gemm2s done)
        int4* p = (int4*)gz.sum;
        for (int i = threadIdx.x; i < ZTAIL_WORDS / 4; i += 256)
            p[i] = make_int4(0, 0, 0, 0);
    }
}

// ---- launch 2: CSR placement (2 edges/thread) + input embedding (fused) ----
#define PLACE_BLOCKS (BB*EE / 512)   // 2500
#define EMB_BLOCKS   (BB*NN / 64)    // 1250
__global__ void __launch_bounds__(256) k_place(const float* __restrict__ x,
                                               const float* __restrict__ inW,
                                               const float* __restrict__ inb) {
    if (blockIdx.x < PLACE_BLOCKS) {
        int i0 = blockIdx.x * 512 + threadIdx.x;   // graph boundary 512-aligned
        int i1 = i0 + 256;
        int b = i0 / (EE);
        b = blockIdx.x / (EE / 512);               // uniform per block
        int d0 = g_dst[i0], d1 = g_dst[i1];
        int s0 = g_src[i0], s1 = g_src[i1];
        int o0 = g_off[b * NN + d0];
        int o1 = g_off[b * NN + d1];
        int r0 = atomicAdd(&gz.fill[b * NN + d0], 1);
        int r1 = atomicAdd(&gz.fill[b * NN + d1], 1);
        g_csr[o0 + r0] = s0;
        g_csr[o1 + r1] = s1;
    } else {
        __shared__ float sW[IND * ED];
        __shared__ float sX[64 * IND];
        int nid0 = (blockIdx.x - PLACE_BLOCKS) * 64;
        int tid = threadIdx.x;
        for (int i = tid; i < IND * ED; i += 256) sW[i] = inW[i];
        for (int i = tid; i < 64 * IND; i += 256) sX[i] = x[(long long)nid0 * IND + i];
        __syncthreads();
        int j = tid & 63;
        float bj = inb[j];
        for (int loc = tid >> 6; loc < 64; loc += 4) {
            float acc = bj;
#pragma unroll
            for (int i = 0; i < IND; i++) acc += sX[loc * IND + i] * sW[i * ED + j];
            g_h0[(long long)(nid0 + loc) * ED + j] = acc;
        }
    }
}

// ---- launch 3 (PROFILED): GEMM1 (fused gather-aggregate, FFMA2 mainloop):
//      h2 = seg_sum(h[src]) @ W1[0:64,:] + s*u + deg*v + b1 ; fused BN stats ----
#define ST1 66
#define G1_SMEMF (8192 + 64*ST1 + 64 + 64 + 64 + 128*5)
__global__ void __launch_bounds__(256) k_gemm1(const float* __restrict__ W1l,
                                               const float* __restrict__ b1l,
                                               const float* __restrict__ hin,
                                               int l) {
    extern __shared__ float sm[];
    float* sW   = sm;                  // 64 x 128
    float* sInT = sW + 8192;           // 64 k x 66 rows (transposed, 8B-aligned pairs)
    float* sS   = sInT + 64 * ST1;
    int*   sOff = (int*)(sS + 64);
    int*   sCnt = sOff + 64;
    float* sU   = (float*)(sCnt + 64);
    float* sV   = sU + 128;
    float* sB   = sV + 128;
    float* sSum = sB + 128;
    float* sSqs = sSum + 128;

    int tid = threadIdx.x;
    int b = blockIdx.y;
    int row0 = blockIdx.x * 64;
    int nrows = NN - row0; if (nrows > 64) nrows = 64;

    for (int i = tid; i < 2048; i += 256) ((float4*)sW)[i] = ((const float4*)W1l)[i];
    for (int i = tid; i < 128; i += 256) {
        sU[i] = g_u[l * H2 + i]; sV[i] = g_v[l * H2 + i]; sB[i] = b1l[i];
        sSum[i] = 0.f; sSqs[i] = 0.f;
    }
    if (tid < 64) {
        int ok = tid < nrows;
        int i = b * NN + row0 + tid;
        sOff[tid] = ok ? g_off[i] : 0;
        sCnt[tid] = ok ? (int)gz.sc[2 * i + 1] : 0;
        sS[tid]   = ok ? gz.sc[2 * i] : 0.f;
    }
    __syncthreads();

    // gather + segment-sum straight from h; 4-way unrolled for MLP;
    // write TRANSPOSED into sInT[k][row]
    {
        int q4 = (tid & 15) * 4;
        int g = tid >> 4;
        const float* hb = hin + (long long)b * NN * ED;
#pragma unroll
        for (int rr = g * 4; rr < g * 4 + 4; rr++) {
            int off = sOff[rr], c = sCnt[rr];
            float ax = 0.f, ay = 0.f, az = 0.f, aw = 0.f;
            int e = 0;
            for (; e + 4 <= c; e += 4) {
                int s0 = g_csr[off + e];
                int s1 = g_csr[off + e + 1];
                int s2 = g_csr[off + e + 2];
                int s3 = g_csr[off + e + 3];
                float4 v0 = *(const float4*)(hb + (long long)s0 * ED + q4);
                float4 v1 = *(const float4*)(hb + (long long)s1 * ED + q4);
                float4 v2 = *(const float4*)(hb + (long long)s2 * ED + q4);
                float4 v3 = *(const float4*)(hb + (long long)s3 * ED + q4);
                ax += v0.x; ay += v0.y; az += v0.z; aw += v0.w;
                ax += v1.x; ay += v1.y; az += v1.z; aw += v1.w;
                ax += v2.x; ay += v2.y; az += v2.z; aw += v2.w;
                ax += v3.x; ay += v3.y; az += v3.z; aw += v3.w;
            }
            for (; e < c; e++) {
                int src = g_csr[off + e];
                float4 v = *(const float4*)(hb + (long long)src * ED + q4);
                ax += v.x; ay += v.y; az += v.z; aw += v.w;
            }
            sInT[(q4 + 0) * ST1 + rr] = ax;
            sInT[(q4 + 1) * ST1 + rr] = ay;
            sInT[(q4 + 2) * ST1 + rr] = az;
            sInT[(q4 + 3) * ST1 + rr] = aw;
        }
    }
    __syncthreads();

    int cq = tid & 31, rg = tid >> 5;   // 32 colquads x 8 rowgroups(8 rows)
    unsigned long long acc2[4][4];      // [rowpair][col]
#pragma unroll
    for (int p = 0; p < 4; p++)
        acc2[p][0] = acc2[p][1] = acc2[p][2] = acc2[p][3] = 0ull;

#pragma unroll 8
    for (int k = 0; k < 64; k++) {
        float4 w = *(const float4*)(sW + k * 128 + cq * 4);
        unsigned long long wb0, wb1, wb2, wb3;
        PK2(wb0, w.x); PK2(wb1, w.y); PK2(wb2, w.z); PK2(wb3, w.w);
        const unsigned long long* arow =
            (const unsigned long long*)(sInT + k * ST1 + rg * 8);
#pragma unroll
        for (int p = 0; p < 4; p++) {
            unsigned long long ap = arow[p];
            FMA2(acc2[p][0], ap, wb0);
            FMA2(acc2[p][1], ap, wb1);
            FMA2(acc2[p][2], ap, wb2);
            FMA2(acc2[p][3], ap, wb3);
        }
    }

    float u0 = sU[cq*4], u1 = sU[cq*4+1], u2 = sU[cq*4+2], u3 = sU[cq*4+3];
    float v0 = sV[cq*4], v1 = sV[cq*4+1], v2 = sV[cq*4+2], v3 = sV[cq*4+3];
    float bb0 = sB[cq*4], bb1 = sB[cq*4+1], bb2 = sB[cq*4+2], bb3 = sB[cq*4+3];
    float ps0=0,ps1=0,ps2=0,ps3=0, pq0=0,pq1=0,pq2=0,pq3=0;
    float* obase = g_h2 + ((long long)b * NN + row0) * H2;
#pragma unroll
    for (int p = 0; p < 4; p++) {
        float o_[2][4];
        UNPK(o_[0][0], o_[1][0], acc2[p][0]);
        UNPK(o_[0][1], o_[1][1], acc2[p][1]);
        UNPK(o_[0][2], o_[1][2], acc2[p][2]);
        UNPK(o_[0][3], o_[1][3], acc2[p][3]);
#pragma unroll
        for (int t = 0; t < 2; t++) {
            int rr = rg * 8 + 2 * p + t;
            if (rr < nrows) {
                float s = sS[rr], d = (float)sCnt[rr];
                float o0 = o_[t][0] + s*u0 + d*v0 + bb0;
                float o1 = o_[t][1] + s*u1 + d*v1 + bb1;
                float o2 = o_[t][2] + s*u2 + d*v2 + bb2;
                float o3 = o_[t][3] + s*u3 + d*v3 + bb3;
                float4 o = {o0, o1, o2, o3};
                *(float4*)(obase + rr * H2 + cq * 4) = o;
                ps0 += o0; ps1 += o1; ps2 += o2; ps3 += o3;
                pq0 += o0*o0; pq1 += o1*o1; pq2 += o2*o2; pq3 += o3*o3;
            }
        }
    }
    atomicAdd(sSum + cq*4,     ps0); atomicAdd(sSum + cq*4 + 1, ps1);
    atomicAdd(sSum + cq*4 + 2, ps2); atomicAdd(sSum + cq*4 + 3, ps3);
    atomicAdd(sSqs + cq*4,     pq0); atomicAdd(sSqs + cq*4 + 1, pq1);
    atomicAdd(sSqs + cq*4 + 2, pq2); atomicAdd(sSqs + cq*4 + 3, pq3);
    __syncthreads();
    float* gsum = gz.sum   + l * BB * H2 + b * H2;
    float* gsq  = gz.sumsq + l * BB * H2 + b * H2;
    for (int i = tid; i < 128; i += 256) {
        atomicAdd(&gsum[i], sSum[i]);
        atomicAdd(&gsq[i],  sSqs[i]);
    }
}

// ---- GEMM2 (BN finalize fused, FFMA2 mainloop, 128x64 tile):
//      out = relu?(relu(BN(h2)) @ W2 + b2)
//      final-layer launch carries 32 extra blocks that zero sc/fill/ctr ----
#define G2ROWS 128
#define GX2 ((NN + G2ROWS - 1) / G2ROWS)   // 157
#define ST2 130
#define ZCLR_BLOCKS 32
#define G2_SMEMF (8192 + 128*ST2 + 256)
__global__ void __launch_bounds__(256) k_gemm2(const float* __restrict__ W2l,
                                               const float* __restrict__ b2l,
                                               const float* __restrict__ gm,
                                               const float* __restrict__ bt,
                                               float* __restrict__ hout,
                                               int l, int relu_out) {
    int tid = threadIdx.x, b = blockIdx.y;
    if (blockIdx.x >= GX2) {                   // final-launch scratch clear
        if (b != 0) return;
        int4* p = (int4*)gz.sc;                // sc+fill+ctr contiguous head
        int zb = blockIdx.x - GX2;
        for (int i = zb * 256 + tid; i < ZHEAD_WORDS / 4; i += ZCLR_BLOCKS * 256)
            p[i] = make_int4(0, 0, 0, 0);
        return;
    }
    extern __shared__ float sm[];
    float* sW   = sm;             // 128 x 64
    float* sInT = sW + 8192;      // 128 k x 130 rows (transposed)
    float* sA   = sInT + 128 * ST2;
    float* sC   = sA + 128;
    int row0 = blockIdx.x * G2ROWS;
    int nrows = NN - row0; if (nrows > G2ROWS) nrows = G2ROWS;

    for (int i = tid; i < 2048; i += 256) ((float4*)sW)[i] = ((const float4*)W2l)[i];
    const float* gsum = gz.sum   + l * BB * H2 + b * H2;
    const float* gsq  = gz.sumsq + l * BB * H2 + b * H2;
    for (int i = tid; i < 128; i += 256) {
        float mean = gsum[i] * (1.0f / NN);
        float var  = gsq[i] * (1.0f / NN) - mean * mean;
        float a = gm[i] * rsqrtf(var + BN_EPS);
        sA[i] = a;
        sC[i] = bt[i] - mean * a;
    }
    __syncthreads();

    // stage BN(h2)+relu TRANSPOSED: r = i&127 (warp-consecutive => conflict-free STS)
    const float* ibase = g_h2 + ((long long)b * NN + row0) * H2;
    for (int i = tid; i < 4096; i += 256) {
        int r = i & 127, k4 = i >> 7;   // k4 in 0..31
        float4 v;
        if (r < nrows) {
            v = ((const float4*)ibase)[r * 32 + k4];
            float4 a4 = ((const float4*)sA)[k4];
            float4 c4 = ((const float4*)sC)[k4];
            v.x = fmaxf(v.x * a4.x + c4.x, 0.f);
            v.y = fmaxf(v.y * a4.y + c4.y, 0.f);
            v.z = fmaxf(v.z * a4.z + c4.z, 0.f);
            v.w = fmaxf(v.w * a4.w + c4.w, 0.f);
        } else v = make_float4(0.f, 0.f, 0.f, 0.f);
        sInT[(k4 * 4 + 0) * ST2 + r] = v.x;
        sInT[(k4 * 4 + 1) * ST2 + r] = v.y;
        sInT[(k4 * 4 + 2) * ST2 + r] = v.z;
        sInT[(k4 * 4 + 3) * ST2 + r] = v.w;
    }
    __syncthreads();

    int cq = tid & 15, rg = tid >> 4;   // 16 colquads x 16 rowgroups(8 rows)
    unsigned long long acc2[4][4];      // [rowpair][col]
#pragma unroll
    for (int p = 0; p < 4; p++)
        acc2[p][0] = acc2[p][1] = acc2[p][2] = acc2[p][3] = 0ull;

#pragma unroll 8
    for (int k = 0; k < 128; k++) {
        float4 w = *(const float4*)(sW + k * 64 + cq * 4);
        unsigned long long wb0, wb1, wb2, wb3;
        PK2(wb0, w.x); PK2(wb1, w.y); PK2(wb2, w.z); PK2(wb3, w.w);
        const unsigned long long* arow =
            (const unsigned long long*)(sInT + k * ST2 + rg * 8);
#pragma unroll
        for (int p = 0; p < 4; p++) {
            unsigned long long ap = arow[p];
            FMA2(acc2[p][0], ap, wb0);
            FMA2(acc2[p][1], ap, wb1);
            FMA2(acc2[p][2], ap, wb2);
            FMA2(acc2[p][3], ap, wb3);
        }
    }

    float4 bb = ((const float4*)b2l)[cq];
    float* obase = hout + ((long long)b * NN + row0) * ED;
#pragma unroll
    for (int p = 0; p < 4; p++) {
        float o_[2][4];
        UNPK(o_[0][0], o_[1][0], acc2[p][0]);
        UNPK(o_[0][1], o_[1][1], acc2[p][1]);
        UNPK(o_[0][2], o_[1][2], acc2[p][2]);
        UNPK(o_[0][3], o_[1][3], acc2[p][3]);
#pragma unroll
        for (int t = 0; t < 2; t++) {
            int rr = rg * 8 + 2 * p + t;
            if (rr < nrows) {
                float4 o = {o_[t][0] + bb.x, o_[t][1] + bb.y,
                            o_[t][2] + bb.z, o_[t][3] + bb.w};
                if (relu_out) {
                    o.x = fmaxf(o.x, 0.f); o.y = fmaxf(o.y, 0.f);
                    o.z = fmaxf(o.z, 0.f); o.w = fmaxf(o.w, 0.f);
                }
                *(float4*)(obase + rr * ED + cq * 4) = o;
            }
        }
    }
}

extern "C" void kernel_launch(void* const* d_in, const int* in_sizes, int n_in,
                              void* d_out, int out_size) {
    const float* x     = (const float*)d_in[0];
    const void*  ei    = d_in[1];
    const float* ea    = (const float*)d_in[2];
    const float* inW   = (const float*)d_in[3];
    const float* inb   = (const float*)d_in[4];
    const float* edgeW = (const float*)d_in[5];
    const float* edgeb = (const float*)d_in[6];
    const float* W1    = (const float*)d_in[7];
    const float* b1    = (const float*)d_in[8];
    const float* gamma = (const float*)d_in[9];
    const float* beta  = (const float*)d_in[10];
    const float* W2    = (const float*)d_in[11];
    const float* b2    = (const float*)d_in[12];
    float* out = (float*)d_out;

    void *ph0, *ph1;
    cudaGetSymbolAddress(&ph0, g_h0);
    cudaGetSymbolAddress(&ph1, g_h1);

    cudaFuncSetAttribute(k_gemm1, cudaFuncAttributeMaxDynamicSharedMemorySize, G1_SMEMF * 4);
    cudaFuncSetAttribute(k_gemm2, cudaFuncAttributeMaxDynamicSharedMemorySize, G2_SMEMF * 4);

    k_prep<<<PREP_BLOCKS, 256>>>(ei, ea);                        // 0
    k_offuv<<<OFF_BLOCKS + NL + 1, 256>>>(edgeW, edgeb, W1);     // 1
    k_place<<<PLACE_BLOCKS + EMB_BLOCKS, 256>>>(x, inW, inb);    // 2

    const float* hin = (const float*)ph0;
    for (int l = 0; l < NL; l++) {
        dim3 g1((NN + 63) / 64, BB);
        k_gemm1<<<g1, 256, G1_SMEMF * 4>>>(W1 + l * H2 * H2, b1 + l * H2, hin, l); // 3 at l=0
        float* hout = (l == NL - 1) ? out : ((l == 0) ? (float*)ph1 : (float*)ph0);
        int fin = (l == NL - 1);
        dim3 g2(GX2 + (fin ? ZCLR_BLOCKS : 0), BB);
        k_gemm2<<<g2, 256, G2_SMEMF * 4>>>(W2 + l * H2 * ED, b2 + l * ED,
                                           gamma + l * H2, beta + l * H2,
                                           hout, l, (l < NL - 1) ? 1 : 0);
        hin = hout;
    }
}